// round 13
// baseline (speedup 1.0000x reference)
#include <cuda_runtime.h>
#include <cstdint>

#define BB 16
#define TT 8
#define CC 1024
#define SPAST 8192
#define SS 8200
#define BT 128
#define CHUNK 256
#define NCHUNK 33          // 32 full chunks cover SPAST; chunk 32 = 8 new rows
#define NPOS (BB * NCHUNK) // 528
#define SCALE 0.03125f
#define KSPLIT 4
#define ATTN_GRID 296      // 148 SMs x 2 CTAs/SM

typedef unsigned long long ull;

// packed f32x2 FMA (GEMMs only — regressed in attn, R7)
#define FMA2(d, a, b) asm("fma.rn.f32x2 %0, %1, %2, %0;" : "+l"(d) : "l"(a), "l"(b))
__device__ __forceinline__ ull packdup(float v) {
    ull r;
    asm("mov.b64 %0, {%1,%1};" : "=l"(r) : "f"(v));
    return r;
}
__device__ __forceinline__ float2 unpack2(ull v) {
    float2 r;
    asm("mov.b64 {%0,%1}, %2;" : "=f"(r.x), "=f"(r.y) : "l"(v));
    return r;
}

// ---------------- scratch ----------------
__device__ float g_q[BT * CC];
__device__ float g_psum[BB * NCHUNK * TT];
__device__ float g_part[(size_t)BB * NCHUNK * TT * CC];   // 17 MB
__device__ float g_ctx[BT * CC];
__device__ float g_qkvp[(size_t)KSPLIT * BT * 3072];
__device__ unsigned g_ticket;

// ---------------- split-K qkv GEMM (FFMA2): part[ks] = x[M,256] x W[256,3072] --
__global__ __launch_bounds__(256) void k_gemm_qkv(const float* __restrict__ A,
                                                  const float* __restrict__ W) {
    __shared__ float xs[64 * 33];
    int tid = threadIdx.x;
    int cl = tid & 15;
    int rg = tid >> 4;
    int n0 = blockIdx.x * 64 + cl * 4;
    int r0 = blockIdx.y * 64;
    int k0 = blockIdx.z * 256;

    ull acc[4][2];
#pragma unroll
    for (int r = 0; r < 4; r++) { acc[r][0] = 0ull; acc[r][1] = 0ull; }

    for (int ks = 0; ks < 256; ks += 32) {
        __syncthreads();
        for (int i = tid; i < 64 * 32; i += 256) {
            int row = i >> 5, kk = i & 31;
            xs[row * 33 + kk] = A[(size_t)(r0 + row) * CC + k0 + ks + kk];
        }
        __syncthreads();
#pragma unroll
        for (int kk = 0; kk < 32; kk++) {
            const ulonglong2 wv = *(const ulonglong2*)&W[(size_t)(k0 + ks + kk) * 3072 + n0];
#pragma unroll
            for (int r = 0; r < 4; r++) {
                ull a2 = packdup(xs[(rg * 4 + r) * 33 + kk]);
                FMA2(acc[r][0], a2, wv.x);
                FMA2(acc[r][1], a2, wv.y);
            }
        }
    }
#pragma unroll
    for (int r = 0; r < 4; r++) {
        int row = r0 + rg * 4 + r;
        *(ulonglong2*)&g_qkvp[((size_t)blockIdx.z * BT + row) * 3072 + n0] =
            make_ulonglong2(acc[r][0], acc[r][1]);
    }
}

// ---------------- qkv reduce + bias + scatter (also resets ticket) ----------
__global__ void k_qkv_red(const float* __restrict__ bias,
                          float* __restrict__ out_k, float* __restrict__ out_v) {
    if (blockIdx.x == 0 && threadIdx.x == 0) g_ticket = 0;
    int g4 = blockIdx.x * 256 + threadIdx.x;
    int row = g4 / 768;
    int n = (g4 - row * 768) * 4;
    float4 s = make_float4(0.f, 0.f, 0.f, 0.f);
#pragma unroll
    for (int ks = 0; ks < KSPLIT; ks++) {
        float4 p = *(const float4*)&g_qkvp[((size_t)ks * BT + row) * 3072 + n];
        s.x += p.x; s.y += p.y; s.z += p.z; s.w += p.w;
    }
    float4 bv = *(const float4*)&bias[n];
    s.x += bv.x; s.y += bv.y; s.z += bv.z; s.w += bv.w;
    int b = row >> 3, t = row & 7;
    if (n < CC)
        *(float4*)&g_q[row * CC + n] = s;
    else if (n < 2 * CC)
        *(float4*)&out_k[((size_t)b * SS + SPAST + t) * CC + (n - CC)] = s;
    else
        *(float4*)&out_v[((size_t)b * SS + SPAST + t) * CC + (n - 2 * CC)] = s;
}

// ---------------- persistent FUSED attention (R9-proven, 2 CTAs/SM) ----------
__global__ __launch_bounds__(256, 2) void k_attn(const float* __restrict__ cache_k,
                                                 const float* __restrict__ cache_v,
                                                 float* __restrict__ out_k,
                                                 float* __restrict__ out_v) {
    __shared__ float sq[TT * CC];      // 32 KB q tile (current batch)
    __shared__ float sp[CHUNK * TT];   // 8 KB probs [row][t]
    __shared__ int s_pos;
    int tid = threadIdx.x;
    int w = tid >> 5, l = tid & 31;
    float4* sq4 = (float4*)sq;
    float4* sp4 = (float4*)sp;
    int cur_b = -1;

    while (true) {
        if (tid == 0) s_pos = (int)atomicAdd(&g_ticket, 1u);
        __syncthreads();
        int pos = s_pos;
        if (pos >= NPOS) break;
        int b = pos / NCHUNK;
        int chunk = pos - b * NCHUNK;
        int s0 = chunk * CHUNK;
        int nrows = (chunk < 32) ? CHUNK : (SS - 32 * CHUNK);   // 256 or 8
        bool cp = (chunk < 32);

        if (b != cur_b) {
            const float4* qsrc = (const float4*)(g_q + (size_t)b * TT * CC);
            for (int i = tid; i < TT * CC / 4; i += 256) sq4[i] = qsrc[i];
            cur_b = b;
        }
        __syncthreads();

        // ---- phase A: stream K rows (4-row blocks, cross-block pipelined) ----
        const float4* kin = cp ? (const float4*)(cache_k + ((size_t)b * SPAST + s0) * CC)
                               : (const float4*)(out_k + ((size_t)b * SS + s0) * CC);
        float4* kout = (float4*)(out_k + ((size_t)b * SS + s0) * CC);

        float4 cur[4], nxt[4];
        if (w * 4 < nrows) {
#pragma unroll
            for (int r = 0; r < 4; r++)
                cur[r] = __ldcs(kin + (size_t)(w * 4 + r) * 256 + l);
        }
        for (int rb = w * 4; rb < nrows; rb += 32) {
            float acc[4][8];
#pragma unroll
            for (int r = 0; r < 4; r++)
#pragma unroll
                for (int t = 0; t < 8; t++) acc[r][t] = 0.f;

#pragma unroll
            for (int j = 0; j < 8; j++) {
                int ci = j * 32 + l;
                if (j < 7) {
                    int cin = ci + 32;
#pragma unroll
                    for (int r = 0; r < 4; r++)
                        nxt[r] = __ldcs(kin + (size_t)(rb + r) * 256 + cin);
                } else if (rb + 32 < nrows) {
#pragma unroll
                    for (int r = 0; r < 4; r++)
                        nxt[r] = __ldcs(kin + (size_t)(rb + 32 + r) * 256 + l);
                }
                if (cp) {
#pragma unroll
                    for (int r = 0; r < 4; r++)
                        __stcs(kout + (size_t)(rb + r) * 256 + ci, cur[r]);
                }
#pragma unroll
                for (int t = 0; t < 8; t++) {
                    float4 qv = sq4[t * 256 + ci];
                    acc[0][t] += cur[0].x * qv.x + cur[0].y * qv.y + cur[0].z * qv.z + cur[0].w * qv.w;
                    acc[1][t] += cur[1].x * qv.x + cur[1].y * qv.y + cur[1].z * qv.z + cur[1].w * qv.w;
                    acc[2][t] += cur[2].x * qv.x + cur[2].y * qv.y + cur[2].z * qv.z + cur[2].w * qv.w;
                    acc[3][t] += cur[3].x * qv.x + cur[3].y * qv.y + cur[3].z * qv.z + cur[3].w * qv.w;
                }
#pragma unroll
                for (int r = 0; r < 4; r++) cur[r] = nxt[r];
            }
#pragma unroll
            for (int r = 0; r < 4; r++)
#pragma unroll
                for (int t = 0; t < 8; t++)
#pragma unroll
                    for (int off = 16; off > 0; off >>= 1)
                        acc[r][t] += __shfl_down_sync(0xffffffffu, acc[r][t], off);
            if (l == 0) {
#pragma unroll
                for (int r = 0; r < 4; r++) {
                    float4* d = (float4*)(sp + (rb + r) * 8);
                    d[0] = make_float4(acc[r][0] * SCALE, acc[r][1] * SCALE,
                                       acc[r][2] * SCALE, acc[r][3] * SCALE);
                    d[1] = make_float4(acc[r][4] * SCALE, acc[r][5] * SCALE,
                                       acc[r][6] * SCALE, acc[r][7] * SCALE);
                }
            }
        }
        __syncthreads();

        // ---- phase B: exp in-place + per-chunk per-t sums ----
        if (w < 8) {
            float s = 0.f;
            for (int r = l; r < nrows; r += 32) {
                float e = __expf(sp[r * 8 + w]);
                sp[r * 8 + w] = e;
                s += e;
            }
#pragma unroll
            for (int off = 16; off > 0; off >>= 1)
                s += __shfl_down_sync(0xffffffffu, s, off);
            if (l == 0) g_psum[(b * NCHUNK + chunk) * TT + w] = s;
        }
        __syncthreads();

        // ---- phase C: stream V rows (4-row blocks, i-prefetch): copy + p*V ----
        const float4* vin = cp ? (const float4*)(cache_v + ((size_t)b * SPAST + s0) * CC)
                               : (const float4*)(out_v + ((size_t)b * SS + s0) * CC);
        float4* vout = (float4*)(out_v + ((size_t)b * SS + s0) * CC);

        float4 acc[8];
#pragma unroll
        for (int t = 0; t < 8; t++) acc[t] = make_float4(0.f, 0.f, 0.f, 0.f);

        float4 vc[4], vn[4];
#pragma unroll
        for (int r = 0; r < 4; r++)
            vc[r] = __ldcs(vin + (size_t)r * 256 + tid);

        for (int i = 0; i < nrows; i += 4) {
            if (i + 4 < nrows) {
#pragma unroll
                for (int r = 0; r < 4; r++)
                    vn[r] = __ldcs(vin + (size_t)(i + 4 + r) * 256 + tid);
            }
            if (cp) {
#pragma unroll
                for (int r = 0; r < 4; r++)
                    __stcs(vout + (size_t)(i + r) * 256 + tid, vc[r]);
            }
#pragma unroll
            for (int r = 0; r < 4; r++) {
                float4 vv = vc[r];
                float4 p0 = sp4[(i + r) * 2], p1 = sp4[(i + r) * 2 + 1];
                acc[0].x += vv.x * p0.x; acc[0].y += vv.y * p0.x; acc[0].z += vv.z * p0.x; acc[0].w += vv.w * p0.x;
                acc[1].x += vv.x * p0.y; acc[1].y += vv.y * p0.y; acc[1].z += vv.z * p0.y; acc[1].w += vv.w * p0.y;
                acc[2].x += vv.x * p0.z; acc[2].y += vv.y * p0.z; acc[2].z += vv.z * p0.z; acc[2].w += vv.w * p0.z;
                acc[3].x += vv.x * p0.w; acc[3].y += vv.y * p0.w; acc[3].z += vv.z * p0.w; acc[3].w += vv.w * p0.w;
                acc[4].x += vv.x * p1.x; acc[4].y += vv.y * p1.x; acc[4].z += vv.z * p1.x; acc[4].w += vv.w * p1.x;
                acc[5].x += vv.x * p1.y; acc[5].y += vv.y * p1.y; acc[5].z += vv.z * p1.y; acc[5].w += vv.w * p1.y;
                acc[6].x += vv.x * p1.z; acc[6].y += vv.y * p1.z; acc[6].z += vv.z * p1.z; acc[6].w += vv.w * p1.z;
                acc[7].x += vv.x * p1.w; acc[7].y += vv.y * p1.w; acc[7].z += vv.z * p1.w; acc[7].w += vv.w * p1.w;
            }
#pragma unroll
            for (int r = 0; r < 4; r++) vc[r] = vn[r];
        }
        float4* dst = (float4*)(g_part + ((size_t)(b * NCHUNK + chunk) * TT) * CC);
#pragma unroll
        for (int t = 0; t < 8; t++) dst[t * 256 + tid] = acc[t];

        __syncthreads();
    }
}

// ---------------- reduce chunk partials -> normalized ctx (2-col ILP) --------
__global__ void k_reduce() {
    int gid = blockIdx.x * 256 + threadIdx.x;   // 0..65535
    int row = gid >> 9;
    int c = gid & 511;
    int b = row >> 3, t = row & 7;
    float S = 0.f;
#pragma unroll
    for (int ch = 0; ch < NCHUNK; ch++)
        S += g_psum[(b * NCHUNK + ch) * TT + t];
    float s0 = 0.f, s1 = 0.f;
#pragma unroll
    for (int ch = 0; ch < NCHUNK; ch++) {
        const float* p = &g_part[((size_t)(b * NCHUNK + ch) * TT + t) * CC];
        s0 += p[c];
        s1 += p[c + 512];
    }
    float inv = 1.0f / S;
    g_ctx[(size_t)row * CC + c] = s0 * inv;
    g_ctx[(size_t)row * CC + c + 512] = s1 * inv;
}

// ---------------- out GEMM (no split-K, bias fused): out = ctx @ w_out + b ----
__global__ __launch_bounds__(256) void k_outg(const float* __restrict__ W,
                                              const float* __restrict__ bias,
                                              float* __restrict__ out) {
    __shared__ float xs[64 * 33];
    int tid = threadIdx.x;
    int cl = tid & 15;
    int rg = tid >> 4;
    int n0 = blockIdx.x * 64 + cl * 4;
    int r0 = blockIdx.y * 64;

    ull acc[4][2];
#pragma unroll
    for (int r = 0; r < 4; r++) { acc[r][0] = 0ull; acc[r][1] = 0ull; }

    for (int ks = 0; ks < CC; ks += 32) {
        __syncthreads();
        for (int i = tid; i < 64 * 32; i += 256) {
            int row = i >> 5, kk = i & 31;
            xs[row * 33 + kk] = g_ctx[(size_t)(r0 + row) * CC + ks + kk];
        }
        __syncthreads();
#pragma unroll
        for (int kk = 0; kk < 32; kk++) {
            const ulonglong2 wv = *(const ulonglong2*)&W[(size_t)(ks + kk) * CC + n0];
#pragma unroll
            for (int r = 0; r < 4; r++) {
                ull a2 = packdup(xs[(rg * 4 + r) * 33 + kk]);
                FMA2(acc[r][0], a2, wv.x);
                FMA2(acc[r][1], a2, wv.y);
            }
        }
    }
    float4 bv = *(const float4*)&bias[n0];
#pragma unroll
    for (int r = 0; r < 4; r++) {
        int row = r0 + rg * 4 + r;
        float2 u0 = unpack2(acc[r][0]);
        float2 u1 = unpack2(acc[r][1]);
        *(float4*)&out[(size_t)row * CC + n0] =
            make_float4(u0.x + bv.x, u0.y + bv.y, u1.x + bv.z, u1.y + bv.w);
    }
}

// ---------------- launch ----------------
extern "C" void kernel_launch(void* const* d_in, const int* in_sizes, int n_in,
                              void* d_out, int out_size) {
    const float* x       = (const float*)d_in[0];
    const float* cache_k = (const float*)d_in[1];
    const float* cache_v = (const float*)d_in[2];
    const float* w_qkv   = (const float*)d_in[3];
    const float* b_qkv   = (const float*)d_in[4];
    const float* w_out   = (const float*)d_in[5];
    const float* b_out   = (const float*)d_in[6];

    float* out_o = (float*)d_out;
    float* out_k = out_o + (size_t)BT * CC;
    float* out_v = out_k + (size_t)BB * SS * CC;

    k_gemm_qkv<<<dim3(48, 2, KSPLIT), 256>>>(x, w_qkv);
    k_qkv_red<<<384, 256>>>(b_qkv, out_k, out_v);
    k_attn<<<ATTN_GRID, 256>>>(cache_k, cache_v, out_k, out_v);
    k_reduce<<<256, 256>>>();
    k_outg<<<dim3(16, 2), 256>>>(w_out, b_out, out_o);
}

// round 16
// speedup vs baseline: 1.2804x; 1.2804x over previous
#include <cuda_runtime.h>
#include <cstdint>

#define BB 16
#define TT 8
#define CC 1024
#define SPAST 8192
#define SS 8200
#define BT 128
#define CHUNK 256
#define NCHUNK 33          // 32 full chunks cover SPAST; chunk 32 = 8 new rows
#define NPOS (BB * NCHUNK) // 528
#define SCALE 0.03125f
#define KSPLIT_QKV 4
#define KSPLIT_OUT 8
#define ATTN_GRID 296      // 148 SMs x 2 CTAs/SM

// ---------------- scratch ----------------
__device__ float g_q[BT * CC];
__device__ float g_psum[BB * NCHUNK * TT];
__device__ float g_part[(size_t)BB * NCHUNK * TT * CC];   // 17 MB
__device__ float g_ctx[BT * CC];
__device__ float g_qkvp[(size_t)KSPLIT_QKV * BT * 3072];
__device__ float g_outp[(size_t)KSPLIT_OUT * BT * CC];
__device__ unsigned g_ticket;

// ---------------- split-K qkv GEMM: part[ks] = x[M,256] x W[256,3072] --------
__global__ __launch_bounds__(256) void k_gemm_qkv(const float* __restrict__ A,
                                                  const float* __restrict__ W) {
    __shared__ float xs[64 * 33];
    int tid = threadIdx.x;
    int cl = tid & 15;
    int rg = tid >> 4;
    int n0 = blockIdx.x * 64 + cl * 4;
    int r0 = blockIdx.y * 64;
    int k0 = blockIdx.z * 256;

    float4 acc[4];
#pragma unroll
    for (int r = 0; r < 4; r++) acc[r] = make_float4(0.f, 0.f, 0.f, 0.f);

    for (int ks = 0; ks < 256; ks += 32) {
        __syncthreads();
        for (int i = tid; i < 64 * 32; i += 256) {
            int row = i >> 5, kk = i & 31;
            xs[row * 33 + kk] = A[(size_t)(r0 + row) * CC + k0 + ks + kk];
        }
        __syncthreads();
#pragma unroll
        for (int kk = 0; kk < 32; kk++) {
            float4 wv = *(const float4*)&W[(size_t)(k0 + ks + kk) * 3072 + n0];
#pragma unroll
            for (int r = 0; r < 4; r++) {
                float a = xs[(rg * 4 + r) * 33 + kk];
                acc[r].x += a * wv.x;
                acc[r].y += a * wv.y;
                acc[r].z += a * wv.z;
                acc[r].w += a * wv.w;
            }
        }
    }
#pragma unroll
    for (int r = 0; r < 4; r++) {
        int row = r0 + rg * 4 + r;
        *(float4*)&g_qkvp[((size_t)blockIdx.z * BT + row) * 3072 + n0] = acc[r];
    }
}

// ---------------- qkv reduce + bias + scatter (also resets ticket) ----------
__global__ void k_qkv_red(const float* __restrict__ bias,
                          float* __restrict__ out_k, float* __restrict__ out_v) {
    if (blockIdx.x == 0 && threadIdx.x == 0) g_ticket = 0;
    int g4 = blockIdx.x * 256 + threadIdx.x;
    int row = g4 / 768;
    int n = (g4 - row * 768) * 4;
    float4 s = make_float4(0.f, 0.f, 0.f, 0.f);
#pragma unroll
    for (int ks = 0; ks < KSPLIT_QKV; ks++) {
        float4 p = *(const float4*)&g_qkvp[((size_t)ks * BT + row) * 3072 + n];
        s.x += p.x; s.y += p.y; s.z += p.z; s.w += p.w;
    }
    float4 bv = *(const float4*)&bias[n];
    s.x += bv.x; s.y += bv.y; s.z += bv.z; s.w += bv.w;
    int b = row >> 3, t = row & 7;
    if (n < CC)
        *(float4*)&g_q[row * CC + n] = s;
    else if (n < 2 * CC)
        *(float4*)&out_k[((size_t)b * SS + SPAST + t) * CC + (n - CC)] = s;
    else
        *(float4*)&out_v[((size_t)b * SS + SPAST + t) * CC + (n - 2 * CC)] = s;
}

// ---------------- split-K out GEMM (256 CTAs): g_outp[ks] = ctx x W_out -------
__global__ __launch_bounds__(256) void k_gemm_out(const float* __restrict__ W) {
    __shared__ float xs[64 * 33];
    int tid = threadIdx.x;
    int cl = tid & 15;
    int rg = tid >> 4;
    int n0 = blockIdx.x * 64 + cl * 4;
    int r0 = blockIdx.y * 64;
    int k0 = blockIdx.z * 128;

    float4 acc[4];
#pragma unroll
    for (int r = 0; r < 4; r++) acc[r] = make_float4(0.f, 0.f, 0.f, 0.f);

    for (int ks = 0; ks < 128; ks += 32) {
        __syncthreads();
        for (int i = tid; i < 64 * 32; i += 256) {
            int row = i >> 5, kk = i & 31;
            xs[row * 33 + kk] = g_ctx[(size_t)(r0 + row) * CC + k0 + ks + kk];
        }
        __syncthreads();
#pragma unroll
        for (int kk = 0; kk < 32; kk++) {
            float4 wv = *(const float4*)&W[(size_t)(k0 + ks + kk) * CC + n0];
#pragma unroll
            for (int r = 0; r < 4; r++) {
                float a = xs[(rg * 4 + r) * 33 + kk];
                acc[r].x += a * wv.x;
                acc[r].y += a * wv.y;
                acc[r].z += a * wv.z;
                acc[r].w += a * wv.w;
            }
        }
    }
#pragma unroll
    for (int r = 0; r < 4; r++) {
        int row = r0 + rg * 4 + r;
        *(float4*)&g_outp[((size_t)blockIdx.z * BT + row) * CC + n0] = acc[r];
    }
}

// ---------------- out reduce ----------------
__global__ void k_out_red(const float* __restrict__ bias, float* __restrict__ out) {
    int g4 = blockIdx.x * 256 + threadIdx.x;
    int row = g4 >> 8;
    int n = (g4 & 255) * 4;
    float4 s = make_float4(0.f, 0.f, 0.f, 0.f);
#pragma unroll
    for (int ks = 0; ks < KSPLIT_OUT; ks++) {
        float4 p = *(const float4*)&g_outp[((size_t)ks * BT + row) * CC + n];
        s.x += p.x; s.y += p.y; s.z += p.z; s.w += p.w;
    }
    float4 bv = *(const float4*)&bias[n];
    s.x += bv.x; s.y += bv.y; s.z += bv.z; s.w += bv.w;
    *(float4*)&out[(size_t)row * CC + n] = s;
}

// ---------------- persistent FUSED attention (422.1-µs proven config) ----------
__global__ __launch_bounds__(256, 2) void k_attn(const float* __restrict__ cache_k,
                                                 const float* __restrict__ cache_v,
                                                 float* __restrict__ out_k,
                                                 float* __restrict__ out_v) {
    __shared__ float sq[TT * CC];      // 32 KB q tile (current batch)
    __shared__ float sp[CHUNK * TT];   // 8 KB probs [row][t]
    __shared__ int s_pos;
    int tid = threadIdx.x;
    int w = tid >> 5, l = tid & 31;
    float4* sq4 = (float4*)sq;
    float4* sp4 = (float4*)sp;
    int cur_b = -1;

    while (true) {
        if (tid == 0) s_pos = (int)atomicAdd(&g_ticket, 1u);
        __syncthreads();
        int pos = s_pos;
        if (pos >= NPOS) break;
        int b = pos / NCHUNK;
        int chunk = pos - b * NCHUNK;
        int s0 = chunk * CHUNK;
        int nrows = (chunk < 32) ? CHUNK : (SS - 32 * CHUNK);   // 256 or 8
        bool cp = (chunk < 32);

        if (b != cur_b) {
            const float4* qsrc = (const float4*)(g_q + (size_t)b * TT * CC);
            for (int i = tid; i < TT * CC / 4; i += 256) sq4[i] = qsrc[i];
            cur_b = b;
        }
        __syncthreads();

        // ---- phase A: stream K rows (4-row blocks, j-prefetch): copy + logits ----
        const float4* kin = cp ? (const float4*)(cache_k + ((size_t)b * SPAST + s0) * CC)
                               : (const float4*)(out_k + ((size_t)b * SS + s0) * CC);
        float4* kout = (float4*)(out_k + ((size_t)b * SS + s0) * CC);
        for (int rb = w * 4; rb < nrows; rb += 32) {
            float acc[4][8];
#pragma unroll
            for (int r = 0; r < 4; r++)
#pragma unroll
                for (int t = 0; t < 8; t++) acc[r][t] = 0.f;

            float4 cur[4], nxt[4];
#pragma unroll
            for (int r = 0; r < 4; r++)
                cur[r] = __ldcs(kin + (size_t)(rb + r) * 256 + l);
#pragma unroll
            for (int j = 0; j < 8; j++) {
                int ci = j * 32 + l;
                if (j < 7) {
                    int cin = ci + 32;
#pragma unroll
                    for (int r = 0; r < 4; r++)
                        nxt[r] = __ldcs(kin + (size_t)(rb + r) * 256 + cin);
                }
                if (cp) {
#pragma unroll
                    for (int r = 0; r < 4; r++)
                        __stcs(kout + (size_t)(rb + r) * 256 + ci, cur[r]);
                }
#pragma unroll
                for (int t = 0; t < 8; t++) {
                    float4 qv = sq4[t * 256 + ci];
                    acc[0][t] += cur[0].x * qv.x + cur[0].y * qv.y + cur[0].z * qv.z + cur[0].w * qv.w;
                    acc[1][t] += cur[1].x * qv.x + cur[1].y * qv.y + cur[1].z * qv.z + cur[1].w * qv.w;
                    acc[2][t] += cur[2].x * qv.x + cur[2].y * qv.y + cur[2].z * qv.z + cur[2].w * qv.w;
                    acc[3][t] += cur[3].x * qv.x + cur[3].y * qv.y + cur[3].z * qv.z + cur[3].w * qv.w;
                }
#pragma unroll
                for (int r = 0; r < 4; r++) cur[r] = nxt[r];
            }
#pragma unroll
            for (int r = 0; r < 4; r++)
#pragma unroll
                for (int t = 0; t < 8; t++)
#pragma unroll
                    for (int off = 16; off > 0; off >>= 1)
                        acc[r][t] += __shfl_down_sync(0xffffffffu, acc[r][t], off);
            if (l == 0) {
#pragma unroll
                for (int r = 0; r < 4; r++) {
                    float4* d = (float4*)(sp + (rb + r) * 8);
                    d[0] = make_float4(acc[r][0] * SCALE, acc[r][1] * SCALE,
                                       acc[r][2] * SCALE, acc[r][3] * SCALE);
                    d[1] = make_float4(acc[r][4] * SCALE, acc[r][5] * SCALE,
                                       acc[r][6] * SCALE, acc[r][7] * SCALE);
                }
            }
        }
        __syncthreads();

        // ---- phase B: exp in-place + per-chunk per-t sums ----
        if (w < 8) {
            float s = 0.f;
            for (int r = l; r < nrows; r += 32) {
                float e = __expf(sp[r * 8 + w]);
                sp[r * 8 + w] = e;
                s += e;
            }
#pragma unroll
            for (int off = 16; off > 0; off >>= 1)
                s += __shfl_down_sync(0xffffffffu, s, off);
            if (l == 0) g_psum[(b * NCHUNK + chunk) * TT + w] = s;
        }
        __syncthreads();

        // ---- phase C: stream V rows (4-row blocks, i-prefetch): copy + p*V ----
        const float4* vin = cp ? (const float4*)(cache_v + ((size_t)b * SPAST + s0) * CC)
                               : (const float4*)(out_v + ((size_t)b * SS + s0) * CC);
        float4* vout = (float4*)(out_v + ((size_t)b * SS + s0) * CC);

        float4 acc[8];
#pragma unroll
        for (int t = 0; t < 8; t++) acc[t] = make_float4(0.f, 0.f, 0.f, 0.f);

        float4 vc[4], vn[4];
#pragma unroll
        for (int r = 0; r < 4; r++)
            vc[r] = __ldcs(vin + (size_t)r * 256 + tid);

        for (int i = 0; i < nrows; i += 4) {
            if (i + 4 < nrows) {
#pragma unroll
                for (int r = 0; r < 4; r++)
                    vn[r] = __ldcs(vin + (size_t)(i + 4 + r) * 256 + tid);
            }
            if (cp) {
#pragma unroll
                for (int r = 0; r < 4; r++)
                    __stcs(vout + (size_t)(i + r) * 256 + tid, vc[r]);
            }
#pragma unroll
            for (int r = 0; r < 4; r++) {
                float4 vv = vc[r];
                float4 p0 = sp4[(i + r) * 2], p1 = sp4[(i + r) * 2 + 1];
                acc[0].x += vv.x * p0.x; acc[0].y += vv.y * p0.x; acc[0].z += vv.z * p0.x; acc[0].w += vv.w * p0.x;
                acc[1].x += vv.x * p0.y; acc[1].y += vv.y * p0.y; acc[1].z += vv.z * p0.y; acc[1].w += vv.w * p0.y;
                acc[2].x += vv.x * p0.z; acc[2].y += vv.y * p0.z; acc[2].z += vv.z * p0.z; acc[2].w += vv.w * p0.z;
                acc[3].x += vv.x * p0.w; acc[3].y += vv.y * p0.w; acc[3].z += vv.z * p0.w; acc[3].w += vv.w * p0.w;
                acc[4].x += vv.x * p1.x; acc[4].y += vv.y * p1.x; acc[4].z += vv.z * p1.x; acc[4].w += vv.w * p1.x;
                acc[5].x += vv.x * p1.y; acc[5].y += vv.y * p1.y; acc[5].z += vv.z * p1.y; acc[5].w += vv.w * p1.y;
                acc[6].x += vv.x * p1.z; acc[6].y += vv.y * p1.z; acc[6].z += vv.z * p1.z; acc[6].w += vv.w * p1.z;
                acc[7].x += vv.x * p1.w; acc[7].y += vv.y * p1.w; acc[7].z += vv.z * p1.w; acc[7].w += vv.w * p1.w;
            }
#pragma unroll
            for (int r = 0; r < 4; r++) vc[r] = vn[r];
        }
        float4* dst = (float4*)(g_part + ((size_t)(b * NCHUNK + chunk) * TT) * CC);
#pragma unroll
        for (int t = 0; t < 8; t++) dst[t * 256 + tid] = acc[t];

        __syncthreads();
    }
}

// ---------------- reduce chunk partials -> normalized ctx (2-col ILP) --------
__global__ void k_reduce() {
    int gid = blockIdx.x * 256 + threadIdx.x;   // 0..65535
    int row = gid >> 9;
    int c = gid & 511;
    int b = row >> 3, t = row & 7;
    float S = 0.f;
#pragma unroll
    for (int ch = 0; ch < NCHUNK; ch++)
        S += g_psum[(b * NCHUNK + ch) * TT + t];
    float s0 = 0.f, s1 = 0.f;
#pragma unroll
    for (int ch = 0; ch < NCHUNK; ch++) {
        const float* p = &g_part[((size_t)(b * NCHUNK + ch) * TT + t) * CC];
        s0 += p[c];
        s1 += p[c + 512];
    }
    float inv = 1.0f / S;
    g_ctx[(size_t)row * CC + c] = s0 * inv;
    g_ctx[(size_t)row * CC + c + 512] = s1 * inv;
}

// ---------------- launch ----------------
extern "C" void kernel_launch(void* const* d_in, const int* in_sizes, int n_in,
                              void* d_out, int out_size) {
    const float* x       = (const float*)d_in[0];
    const float* cache_k = (const float*)d_in[1];
    const float* cache_v = (const float*)d_in[2];
    const float* w_qkv   = (const float*)d_in[3];
    const float* b_qkv   = (const float*)d_in[4];
    const float* w_out   = (const float*)d_in[5];
    const float* b_out   = (const float*)d_in[6];

    float* out_o = (float*)d_out;
    float* out_k = out_o + (size_t)BT * CC;
    float* out_v = out_k + (size_t)BB * SS * CC;

    k_gemm_qkv<<<dim3(48, 2, KSPLIT_QKV), 256>>>(x, w_qkv);
    k_qkv_red<<<384, 256>>>(b_qkv, out_k, out_v);
    k_attn<<<ATTN_GRID, 256>>>(cache_k, cache_v, out_k, out_v);
    k_reduce<<<256, 256>>>();
    k_gemm_out<<<dim3(16, 2, KSPLIT_OUT), 256>>>(w_out);
    k_out_red<<<128, 256>>>(b_out, out_o);
}